// round 9
// baseline (speedup 1.0000x reference)
#include <cuda_runtime.h>
#include <cstdint>

#define NB   2
#define SEQ  2048
#define DM   1024
#define NH   16
#define DHD  64

// Scratch (allocation-free rule: __device__ globals)
static __device__ float g_X[(size_t)NB*SEQ*DM];      // tf32-rounded x
static __device__ float g_Q[NB*NH*SEQ*DHD];          // [b][h][s][e], rounded
static __device__ float g_K[NB*NH*SEQ*DHD];          // [b][h][s][e], rounded
static __device__ float g_V[NB*NH*SEQ*DHD];          // [b][h][s][e], rounded
static __device__ float g_Z[(size_t)NB*SEQ*DM];      // rounded
// Rounded weight copies, SAME layout as originals
static __device__ float g_WrQ[(size_t)DM*DM];
static __device__ float g_WrK[(size_t)DM*DM];
static __device__ float g_WrV[(size_t)DM*DM];
static __device__ float g_WrO[(size_t)DM*DM];

// ---------------------------------------------------------------------------
// helpers
// ---------------------------------------------------------------------------
__device__ __forceinline__ float to_tf32(float x){
    float y; asm("cvt.rna.tf32.f32 %0, %1;" : "=f"(y) : "f"(x)); return y;
}
__device__ __forceinline__ float4 tf4(float4 v){
    return make_float4(to_tf32(v.x), to_tf32(v.y), to_tf32(v.z), to_tf32(v.w));
}
__device__ __forceinline__ unsigned fu(float x){ return __float_as_uint(x); }
__device__ __forceinline__ float fast_ex2(float x){
    float y; asm("ex2.approx.f32 %0, %1;" : "=f"(y) : "f"(x)); return y;
}
__device__ __forceinline__ void mma8(float* c,
    unsigned a0, unsigned a1, unsigned a2, unsigned a3,
    unsigned b0, unsigned b1)
{
    asm volatile(
      "mma.sync.aligned.m16n8k8.row.col.f32.tf32.tf32.f32 "
      "{%0,%1,%2,%3},{%4,%5,%6,%7},{%8,%9},{%0,%1,%2,%3};"
      : "+f"(c[0]), "+f"(c[1]), "+f"(c[2]), "+f"(c[3])
      : "r"(a0), "r"(a1), "r"(a2), "r"(a3), "r"(b0), "r"(b1));
}
__device__ __forceinline__ void ldsm4(unsigned &d0, unsigned &d1, unsigned &d2, unsigned &d3,
                                      const float* p)
{
    unsigned a = (unsigned)__cvta_generic_to_shared(p);
    asm volatile("ldmatrix.sync.aligned.m8n8.x4.shared.b16 {%0,%1,%2,%3}, [%4];"
        : "=r"(d0), "=r"(d1), "=r"(d2), "=r"(d3) : "r"(a));
}
__device__ __forceinline__ void cpa16(const float* smem_dst, const void* gsrc){
    unsigned s = (unsigned)__cvta_generic_to_shared(smem_dst);
    asm volatile("cp.async.cg.shared.global [%0], [%1], 16;" :: "r"(s), "l"(gsrc) : "memory");
}
#define CP_COMMIT() asm volatile("cp.async.commit_group;" ::: "memory")
#define CP_WAIT0()  asm volatile("cp.async.wait_group 0;" ::: "memory")
#define CP_WAIT1()  asm volatile("cp.async.wait_group 1;" ::: "memory")

// ---------------------------------------------------------------------------
// Pre-pass: round x and all weights to tf32 once (same layouts).
// ---------------------------------------------------------------------------
__global__ __launch_bounds__(256) void round_x_kernel(const float* __restrict__ x)
{
    int i = blockIdx.x * 256 + threadIdx.x;     // 1,048,576 float4
    ((float4*)g_X)[i] = tf4(((const float4*)x)[i]);
}
__global__ __launch_bounds__(256) void round_w_kernel(
    const float* __restrict__ Wq, const float* __restrict__ Wk,
    const float* __restrict__ Wv, const float* __restrict__ Wo)
{
    int i = blockIdx.x * 256 + threadIdx.x;     // 262,144 float4 per tensor
    int z = blockIdx.y;
    const float* src = (z==0)?Wq:(z==1)?Wk:(z==2)?Wv:Wo;
    float* dst       = (z==0)?g_WrQ:(z==1)?g_WrK:(z==2)?g_WrV:g_WrO;
    ((float4*)dst)[i] = tf4(((const float4*)src)[i]);
}

// ---------------------------------------------------------------------------
// GEMM smem geometry (R5-proven): A [128][36] ldsm, B [32][136] scalar LDS.
// Double buffered, staged via cp.async with depth-1 prefetch.
// ---------------------------------------------------------------------------
#define GEMM_SMEM ((2*(128*36) + 2*(32*136)) * 4)   // 71680 B

// ---------------------------------------------------------------------------
// Kernel 1: QKV projection. grid (32, 8, 3), 128x128 tiles.
// ---------------------------------------------------------------------------
__global__ __launch_bounds__(256) void qkv_kernel(
    const float* __restrict__ bq, const float* __restrict__ bk, const float* __restrict__ bv)
{
    extern __shared__ float sm[];
    float* Abuf[2] = { sm,        sm + 4608 };
    float* Bbuf[2] = { sm + 9216, sm + 9216 + 4352 };

    const int tid  = threadIdx.x;
    const int warp = tid >> 5, lane = tid & 31;
    const int g = lane >> 2, tg = lane & 3;
    const int wm = warp >> 1, wn = warp & 1;
    const int row0 = blockIdx.x * 128;
    const int col0 = blockIdx.y * 128;
    const int z = blockIdx.z;

    const float* W    = (z==0)?g_WrQ:(z==1)?g_WrK:g_WrV;
    const float* bias = (z==0)?bq:(z==1)?bk:bv;
    float* Out        = (z==0)?g_Q:(z==1)?g_K:g_V;

    const int rA  = tid >> 3;            // 0..31 (+32u)
    const int kqA = (tid & 7) * 4;
    const int kB  = warp;                // +8u k rows
    const int cB  = lane * 4;
    const int ccg = col0 + cB;
    const int bh  = ccg >> 6, be = ccg & 63;
    const int a_r = ((lane >> 3) & 1) * 8 + (lane & 7);
    const int a_k = ((lane >> 4) & 1) * 4;

    float acc[2][8][4];
    #pragma unroll
    for (int i = 0; i < 2; i++)
        #pragma unroll
        for (int j = 0; j < 8; j++)
            #pragma unroll
            for (int k = 0; k < 4; k++) acc[i][j][k] = 0.f;

    #pragma unroll
    for (int u = 0; u < 4; u++)
        cpa16(Abuf[0] + (rA + 32*u) * 36 + kqA,
              g_X + (size_t)(row0 + rA + 32*u) * DM + kqA);
    #pragma unroll
    for (int u = 0; u < 4; u++)
        cpa16(Bbuf[0] + (kB + 8*u) * 136 + cB,
              W + ((size_t)bh * DM + kB + 8*u) * DHD + be);
    CP_COMMIT();

    for (int s = 0; s < 32; s++) {
        CP_WAIT0();
        __syncthreads();
        if (s < 31) {
            const int k0 = (s + 1) * 32;
            float* An = Abuf[(s+1) & 1];
            float* Bn = Bbuf[(s+1) & 1];
            #pragma unroll
            for (int u = 0; u < 4; u++)
                cpa16(An + (rA + 32*u) * 36 + kqA,
                      g_X + (size_t)(row0 + rA + 32*u) * DM + k0 + kqA);
            #pragma unroll
            for (int u = 0; u < 4; u++)
                cpa16(Bn + (kB + 8*u) * 136 + cB,
                      W + ((size_t)bh * DM + k0 + kB + 8*u) * DHD + be);
            CP_COMMIT();
        }
        const float* Acur = Abuf[s & 1];
        const float* Bcur = Bbuf[s & 1];
        #pragma unroll
        for (int ks = 0; ks < 4; ks++) {
            unsigned x0,x1,x2,x3, y0,y1,y2,y3;
            ldsm4(x0,x1,x2,x3, Acur + (wm*32      + a_r) * 36 + ks*8 + a_k);
            ldsm4(y0,y1,y2,y3, Acur + (wm*32 + 16 + a_r) * 36 + ks*8 + a_k);
            #pragma unroll
            for (int nt = 0; nt < 8; nt++) {
                int c = wn * 64 + nt * 8 + g;
                unsigned b0 = fu(Bcur[(ks*8 + tg    ) * 136 + c]);
                unsigned b1 = fu(Bcur[(ks*8 + tg + 4) * 136 + c]);
                mma8(acc[0][nt], x0,x1,x2,x3, b0,b1);
                mma8(acc[1][nt], y0,y1,y2,y3, b0,b1);
            }
        }
    }

    #pragma unroll
    for (int mt = 0; mt < 2; mt++) {
        int r = row0 + wm * 32 + mt * 16 + g;
        int b_ = r >> 11, sq = r & 2047;
        #pragma unroll
        for (int nt = 0; nt < 8; nt++) {
            int cg = col0 + wn * 64 + nt * 8 + tg * 2;
            int h = cg >> 6, e = cg & 63;
            float bv0 = bias[cg], bv1 = bias[cg + 1];
            size_t base = ((size_t)b_ * NH + h) * SEQ;
            *(float2*)(Out + (base + sq    ) * DHD + e) =
                make_float2(to_tf32(acc[mt][nt][0] + bv0), to_tf32(acc[mt][nt][1] + bv1));
            *(float2*)(Out + (base + sq + 8) * DHD + e) =
                make_float2(to_tf32(acc[mt][nt][2] + bv0), to_tf32(acc[mt][nt][3] + bv1));
        }
    }
}

// ---------------------------------------------------------------------------
// Kernel 2: causal flash attention. 128-thread CTAs (4 warps, 64 q-rows),
// 2 CTAs/SM. P re-layout C-frag -> A-frag via quad shuffles (no smem).
// Pipelined cp.async K/V staging.
// ---------------------------------------------------------------------------
#define KS_STRIDE 68
#define VS_STRIDE 72
#define ATTN_SMEM ((128*KS_STRIDE + 128*VS_STRIDE) * 4)   // 71680 B

__global__ __launch_bounds__(128, 2) void attn_kernel()
{
    extern __shared__ float sma[];
    float* Ks = sma;
    float* Vs = Ks + 128 * KS_STRIDE;

    const int tid  = threadIdx.x;            // 0..127
    const int warp = tid >> 5, lane = tid & 31;
    const int g = lane >> 2, tg = lane & 3;
    const int k_c = ((lane >> 4) & 1) * 8 + (lane & 7);
    const int k_k = ((lane >> 3) & 1) * 4;
    // shuffle source lanes for C-frag -> A-frag conversion
    const int sidx0 = (lane & ~3) | (tg >> 1);
    const int sidx1 = sidx0 + 2;
    const bool oddt = (tg & 1) != 0;

    const int idx = blockIdx.x;              // 0..1023
    const int qt  = 31 - (idx >> 5);         // heaviest q-tiles first
    const int bh  = idx & 31;
    const int jmax = qt >> 1;                // k-tiles of 128

    const float* Qp = g_Q + (size_t)bh * SEQ * DHD;
    const float* Kp = g_K + (size_t)bh * SEQ * DHD;
    const float* Vp = g_V + (size_t)bh * SEQ * DHD;

    const int qrow = qt * 64 + warp * 16 + g;

    // Q fragments (pre-rounded in gmem)
    unsigned qa[8][4];
    #pragma unroll
    for (int ks = 0; ks < 8; ks++) {
        qa[ks][0] = fu(Qp[(size_t)(qrow    ) * DHD + ks * 8 + tg    ]);
        qa[ks][1] = fu(Qp[(size_t)(qrow + 8) * DHD + ks * 8 + tg    ]);
        qa[ks][2] = fu(Qp[(size_t)(qrow    ) * DHD + ks * 8 + tg + 4]);
        qa[ks][3] = fu(Qp[(size_t)(qrow + 8) * DHD + ks * 8 + tg + 4]);
    }

    const float SCL = 0.125f * 1.4426950408889634f;
    float m0 = -1e30f, m1 = -1e30f, l0 = 0.f, l1 = 0.f;
    float o[8][4];
    #pragma unroll
    for (int nt = 0; nt < 8; nt++)
        #pragma unroll
        for (int cc = 0; cc < 4; cc++) o[nt][cc] = 0.f;

    // prologue: stage K(0), V(0)  (2048 float4 each, 16 per thread)
    {
        const float4* K4 = (const float4*)Kp;
        #pragma unroll
        for (int u = 0; u < 16; u++) {
            int i = tid + u * 128;
            int r = i >> 4, q = i & 15;
            cpa16(&Ks[r * KS_STRIDE + q * 4], K4 + i);
        }
        CP_COMMIT();
        const float4* V4 = (const float4*)Vp;
        #pragma unroll
        for (int u = 0; u < 16; u++) {
            int i = tid + u * 128;
            int r = i >> 4, q = i & 15;
            cpa16(&Vs[r * VS_STRIDE + q * 4], V4 + i);
        }
        CP_COMMIT();
    }

    for (int j = 0; j <= jmax; j++) {
        CP_WAIT1();                       // K(j) landed (V(j) may be in flight)
        __syncthreads();

        // S = Q K^T  (16 rows x 128 cols per warp)
        float sacc[16][4];
        #pragma unroll
        for (int nt = 0; nt < 16; nt++)
            #pragma unroll
            for (int cc = 0; cc < 4; cc++) sacc[nt][cc] = 0.f;

        #pragma unroll
        for (int ntp = 0; ntp < 8; ntp++) {
            #pragma unroll
            for (int ks = 0; ks < 8; ks++) {
                unsigned b0,b1,b2,b3;
                ldsm4(b0,b1,b2,b3, Ks + (ntp*16 + k_c) * KS_STRIDE + ks*8 + k_k);
                mma8(sacc[2*ntp    ], qa[ks][0],qa[ks][1],qa[ks][2],qa[ks][3], b0,b1);
                mma8(sacc[2*ntp + 1], qa[ks][0],qa[ks][1],qa[ks][2],qa[ks][3], b2,b3);
            }
        }
        __syncthreads();                  // all warps done reading Ks
        if (j < jmax) {                   // prefetch K(j+1)
            const float4* K4 = (const float4*)(Kp + (size_t)(j+1) * 128 * DHD);
            #pragma unroll
            for (int u = 0; u < 16; u++) {
                int i = tid + u * 128;
                int r = i >> 4, q = i & 15;
                cpa16(&Ks[r * KS_STRIDE + q * 4], K4 + i);
            }
            CP_COMMIT();
        }

        // scale + causal mask (final tile only; earlier tiles provably unmasked)
        const bool diag = (j == jmax);
        #pragma unroll
        for (int nt = 0; nt < 16; nt++) {
            #pragma unroll
            for (int cc = 0; cc < 4; cc++) sacc[nt][cc] *= SCL;
            if (diag) {
                int kc = j * 128 + nt * 8 + tg * 2;
                if (kc     > qrow    ) sacc[nt][0] = -1e30f;
                if (kc + 1 > qrow    ) sacc[nt][1] = -1e30f;
                if (kc     > qrow + 8) sacc[nt][2] = -1e30f;
                if (kc + 1 > qrow + 8) sacc[nt][3] = -1e30f;
            }
        }

        // row max (quad butterfly)
        float rm0 = -1e30f, rm1 = -1e30f;
        #pragma unroll
        for (int nt = 0; nt < 16; nt++) {
            rm0 = fmaxf(rm0, fmaxf(sacc[nt][0], sacc[nt][1]));
            rm1 = fmaxf(rm1, fmaxf(sacc[nt][2], sacc[nt][3]));
        }
        rm0 = fmaxf(rm0, __shfl_xor_sync(0xffffffffu, rm0, 1));
        rm0 = fmaxf(rm0, __shfl_xor_sync(0xffffffffu, rm0, 2));
        rm1 = fmaxf(rm1, __shfl_xor_sync(0xffffffffu, rm1, 1));
        rm1 = fmaxf(rm1, __shfl_xor_sync(0xffffffffu, rm1, 2));

        float mn0 = fmaxf(m0, rm0), mn1 = fmaxf(m1, rm1);
        float al0 = fast_ex2(m0 - mn0), al1 = fast_ex2(m1 - mn1);
        l0 *= al0; l1 *= al1;
        #pragma unroll
        for (int nt = 0; nt < 8; nt++) {
            o[nt][0] *= al0; o[nt][1] *= al0;
            o[nt][2] *= al1; o[nt][3] *= al1;
        }

        // P = exp2(s - m), tf32-rounded in-register; accumulate row sums;
        // then convert C-frag -> A-frag via quad shuffles (in place).
        float rs0 = 0.f, rs1 = 0.f;
        #pragma unroll
        for (int nt = 0; nt < 16; nt++) {
            float p0 = fast_ex2(sacc[nt][0] - mn0);
            float p1 = fast_ex2(sacc[nt][1] - mn0);
            float p2 = fast_ex2(sacc[nt][2] - mn1);
            float p3 = fast_ex2(sacc[nt][3] - mn1);
            rs0 += p0 + p1; rs1 += p2 + p3;
            float c0 = to_tf32(p0), c1 = to_tf32(p1);
            float c2 = to_tf32(p2), c3 = to_tf32(p3);
            // A-frag: a0=P[g][tg], a1=P[g+8][tg], a2=P[g][tg+4], a3=P[g+8][tg+4]
            float s00 = __shfl_sync(0xffffffffu, c0, sidx0);
            float s01 = __shfl_sync(0xffffffffu, c1, sidx0);
            float s10 = __shfl_sync(0xffffffffu, c2, sidx0);
            float s11 = __shfl_sync(0xffffffffu, c3, sidx0);
            float s20 = __shfl_sync(0xffffffffu, c0, sidx1);
            float s21 = __shfl_sync(0xffffffffu, c1, sidx1);
            float s30 = __shfl_sync(0xffffffffu, c2, sidx1);
            float s31 = __shfl_sync(0xffffffffu, c3, sidx1);
            sacc[nt][0] = oddt ? s01 : s00;
            sacc[nt][1] = oddt ? s11 : s10;
            sacc[nt][2] = oddt ? s21 : s20;
            sacc[nt][3] = oddt ? s31 : s30;
        }
        rs0 += __shfl_xor_sync(0xffffffffu, rs0, 1);
        rs0 += __shfl_xor_sync(0xffffffffu, rs0, 2);
        rs1 += __shfl_xor_sync(0xffffffffu, rs1, 1);
        rs1 += __shfl_xor_sync(0xffffffffu, rs1, 2);
        l0 += rs0; l1 += rs1;
        m0 = mn0;  m1 = mn1;

        // wait for V(j), then barrier for visibility
        if (j < jmax) { CP_WAIT1(); } else { CP_WAIT0(); }
        __syncthreads();

        // O += P V   (A-frags in registers now)
        #pragma unroll
        for (int ks = 0; ks < 16; ks++) {
            unsigned p0 = fu(sacc[ks][0]), p1 = fu(sacc[ks][1]);
            unsigned p2 = fu(sacc[ks][2]), p3 = fu(sacc[ks][3]);
            #pragma unroll
            for (int nt = 0; nt < 8; nt++) {
                unsigned b0 = fu(Vs[(ks*8 + tg    ) * VS_STRIDE + nt*8 + g]);
                unsigned b1 = fu(Vs[(ks*8 + tg + 4) * VS_STRIDE + nt*8 + g]);
                mma8(o[nt], p0,p1,p2,p3, b0,b1);
            }
        }
        __syncthreads();                  // all warps done reading Vs
        if (j < jmax) {                   // prefetch V(j+1)
            const float4* V4 = (const float4*)(Vp + (size_t)(j+1) * 128 * DHD);
            #pragma unroll
            for (int u = 0; u < 16; u++) {
                int i = tid + u * 128;
                int r = i >> 4, q = i & 15;
                cpa16(&Vs[r * VS_STRIDE + q * 4], V4 + i);
            }
            CP_COMMIT();
        }
    }

    // normalize + round + write Z in [b][s][h*64+e] layout
    float inv0 = 1.f / l0, inv1 = 1.f / l1;
    const int b_ = bh >> 4, h = bh & 15;
    size_t base = ((size_t)b_ * SEQ + qrow) * DM + h * DHD;
    #pragma unroll
    for (int nt = 0; nt < 8; nt++) {
        int e = nt * 8 + tg * 2;
        *(float2*)(g_Z + base + e) =
            make_float2(to_tf32(o[nt][0] * inv0), to_tf32(o[nt][1] * inv0));
        *(float2*)(g_Z + base + (size_t)8 * DM + e) =
            make_float2(to_tf32(o[nt][2] * inv1), to_tf32(o[nt][3] * inv1));
    }
}

// ---------------------------------------------------------------------------
// Kernel 3: output projection (same structure as qkv).
// ---------------------------------------------------------------------------
__global__ __launch_bounds__(256) void oproj_kernel(
    const float* __restrict__ bo, float* __restrict__ out)
{
    extern __shared__ float sm[];
    float* Abuf[2] = { sm,        sm + 4608 };
    float* Bbuf[2] = { sm + 9216, sm + 9216 + 4352 };

    const int tid  = threadIdx.x;
    const int warp = tid >> 5, lane = tid & 31;
    const int g = lane >> 2, tg = lane & 3;
    const int wm = warp >> 1, wn = warp & 1;
    const int row0 = blockIdx.x * 128;
    const int col0 = blockIdx.y * 128;

    const int rA  = tid >> 3;
    const int kqA = (tid & 7) * 4;
    const int kB  = warp;
    const int cB  = lane * 4;
    const int a_r = ((lane >> 3) & 1) * 8 + (lane & 7);
    const int a_k = ((lane >> 4) & 1) * 4;

    float acc[2][8][4];
    #pragma unroll
    for (int i = 0; i < 2; i++)
        #pragma unroll
        for (int j = 0; j < 8; j++)
            #pragma unroll
            for (int k = 0; k < 4; k++) acc[i][j][k] = 0.f;

    #pragma unroll
    for (int u = 0; u < 4; u++)
        cpa16(Abuf[0] + (rA + 32*u) * 36 + kqA,
              g_Z + (size_t)(row0 + rA + 32*u) * DM + kqA);
    #pragma unroll
    for (int u = 0; u < 4; u++)
        cpa16(Bbuf[0] + (kB + 8*u) * 136 + cB,
              g_WrO + (size_t)(kB + 8*u) * DM + col0 + cB);
    CP_COMMIT();

    for (int s = 0; s < 32; s++) {
        CP_WAIT0();
        __syncthreads();
        if (s < 31) {
            const int k0 = (s + 1) * 32;
            float* An = Abuf[(s+1) & 1];
            float* Bn = Bbuf[(s+1) & 1];
            #pragma unroll
            for (int u = 0; u < 4; u++)
                cpa16(An + (rA + 32*u) * 36 + kqA,
                      g_Z + (size_t)(row0 + rA + 32*u) * DM + k0 + kqA);
            #pragma unroll
            for (int u = 0; u < 4; u++)
                cpa16(Bn + (kB + 8*u) * 136 + cB,
                      g_WrO + (size_t)(k0 + kB + 8*u) * DM + col0 + cB);
            CP_COMMIT();
        }
        const float* Acur = Abuf[s & 1];
        const float* Bcur = Bbuf[s & 1];
        #pragma unroll
        for (int ks = 0; ks < 4; ks++) {
            unsigned x0,x1,x2,x3, y0,y1,y2,y3;
            ldsm4(x0,x1,x2,x3, Acur + (wm*32      + a_r) * 36 + ks*8 + a_k);
            ldsm4(y0,y1,y2,y3, Acur + (wm*32 + 16 + a_r) * 36 + ks*8 + a_k);
            #pragma unroll
            for (int nt = 0; nt < 8; nt++) {
                int c = wn * 64 + nt * 8 + g;
                unsigned b0 = fu(Bcur[(ks*8 + tg    ) * 136 + c]);
                unsigned b1 = fu(Bcur[(ks*8 + tg + 4) * 136 + c]);
                mma8(acc[0][nt], x0,x1,x2,x3, b0,b1);
                mma8(acc[1][nt], y0,y1,y2,y3, b0,b1);
            }
        }
    }

    #pragma unroll
    for (int mt = 0; mt < 2; mt++) {
        int r = row0 + wm * 32 + mt * 16 + g;
        #pragma unroll
        for (int nt = 0; nt < 8; nt++) {
            int cg = col0 + wn * 64 + nt * 8 + tg * 2;
            float bv0 = bo[cg], bv1 = bo[cg + 1];
            *(float2*)(out + (size_t)(r    ) * DM + cg) =
                make_float2(acc[mt][nt][0] + bv0, acc[mt][nt][1] + bv1);
            *(float2*)(out + (size_t)(r + 8) * DM + cg) =
                make_float2(acc[mt][nt][2] + bv0, acc[mt][nt][3] + bv1);
        }
    }
}

// ---------------------------------------------------------------------------
extern "C" void kernel_launch(void* const* d_in, const int* in_sizes, int n_in,
                              void* d_out, int out_size)
{
    (void)in_sizes; (void)n_in; (void)out_size;
    const float* x  = (const float*)d_in[0];
    const float* Wq = (const float*)d_in[1];
    const float* Wk = (const float*)d_in[2];
    const float* Wv = (const float*)d_in[3];
    const float* Wo = (const float*)d_in[4];
    const float* bq = (const float*)d_in[5];
    const float* bk = (const float*)d_in[6];
    const float* bv = (const float*)d_in[7];
    const float* bo = (const float*)d_in[8];
    float* out = (float*)d_out;

    static bool attr_done = false;
    if (!attr_done) {
        cudaFuncSetAttribute(qkv_kernel,
            cudaFuncAttributeMaxDynamicSharedMemorySize, GEMM_SMEM);
        cudaFuncSetAttribute(attn_kernel,
            cudaFuncAttributeMaxDynamicSharedMemorySize, ATTN_SMEM);
        cudaFuncSetAttribute(oproj_kernel,
            cudaFuncAttributeMaxDynamicSharedMemorySize, GEMM_SMEM);
        attr_done = true;
    }

    round_x_kernel<<<4096, 256>>>(x);
    dim3 grw(1024, 4);
    round_w_kernel<<<grw, 256>>>(Wq, Wk, Wv, Wo);

    dim3 g1(32, 8, 3);
    qkv_kernel<<<g1, 256, GEMM_SMEM>>>(bq, bk, bv);

    attn_kernel<<<1024, 128, ATTN_SMEM>>>();

    dim3 g3(32, 8);
    oproj_kernel<<<g3, 256, GEMM_SMEM>>>(bo, out);
}

// round 11
// speedup vs baseline: 1.0161x; 1.0161x over previous
#include <cuda_runtime.h>
#include <cstdint>

#define NB   2
#define SEQ  2048
#define DM   1024
#define NH   16
#define DHD  64

// Scratch (allocation-free rule: __device__ globals)
static __device__ float g_X[(size_t)NB*SEQ*DM];      // tf32-rounded x
static __device__ float g_Q[NB*NH*SEQ*DHD];          // [b][h][s][e], rounded, pre-scaled
static __device__ float g_K[NB*NH*SEQ*DHD];          // [b][h][s][e], rounded
static __device__ float g_V[NB*NH*SEQ*DHD];          // [b][h][e][s], rounded (TRANSPOSED)
static __device__ float g_Z[(size_t)NB*SEQ*DM];      // rounded
// Rounded weight copies, SAME layout as originals
static __device__ float g_WrQ[(size_t)DM*DM];
static __device__ float g_WrK[(size_t)DM*DM];
static __device__ float g_WrV[(size_t)DM*DM];
static __device__ float g_WrO[(size_t)DM*DM];

// ---------------------------------------------------------------------------
// helpers
// ---------------------------------------------------------------------------
__device__ __forceinline__ float to_tf32(float x){
    float y; asm("cvt.rna.tf32.f32 %0, %1;" : "=f"(y) : "f"(x)); return y;
}
__device__ __forceinline__ float4 tf4(float4 v){
    return make_float4(to_tf32(v.x), to_tf32(v.y), to_tf32(v.z), to_tf32(v.w));
}
__device__ __forceinline__ unsigned fu(float x){ return __float_as_uint(x); }
__device__ __forceinline__ float fast_ex2(float x){
    float y; asm("ex2.approx.f32 %0, %1;" : "=f"(y) : "f"(x)); return y;
}
__device__ __forceinline__ void mma8(float* c,
    unsigned a0, unsigned a1, unsigned a2, unsigned a3,
    unsigned b0, unsigned b1)
{
    asm volatile(
      "mma.sync.aligned.m16n8k8.row.col.f32.tf32.tf32.f32 "
      "{%0,%1,%2,%3},{%4,%5,%6,%7},{%8,%9},{%0,%1,%2,%3};"
      : "+f"(c[0]), "+f"(c[1]), "+f"(c[2]), "+f"(c[3])
      : "r"(a0), "r"(a1), "r"(a2), "r"(a3), "r"(b0), "r"(b1));
}
__device__ __forceinline__ void ldsm4(unsigned &d0, unsigned &d1, unsigned &d2, unsigned &d3,
                                      const float* p)
{
    unsigned a = (unsigned)__cvta_generic_to_shared(p);
    asm volatile("ldmatrix.sync.aligned.m8n8.x4.shared.b16 {%0,%1,%2,%3}, [%4];"
        : "=r"(d0), "=r"(d1), "=r"(d2), "=r"(d3) : "r"(a));
}
__device__ __forceinline__ void cpa16(const float* smem_dst, const void* gsrc){
    unsigned s = (unsigned)__cvta_generic_to_shared(smem_dst);
    asm volatile("cp.async.cg.shared.global [%0], [%1], 16;" :: "r"(s), "l"(gsrc) : "memory");
}
#define CP_COMMIT() asm volatile("cp.async.commit_group;" ::: "memory")
#define CP_WAIT0()  asm volatile("cp.async.wait_group 0;" ::: "memory")
#define CP_WAIT1()  asm volatile("cp.async.wait_group 1;" ::: "memory")

// ---------------------------------------------------------------------------
// Pre-pass: round x and all weights to tf32 once (same layouts).
// ---------------------------------------------------------------------------
__global__ __launch_bounds__(256) void round_x_kernel(const float* __restrict__ x)
{
    int i = blockIdx.x * 256 + threadIdx.x;     // 1,048,576 float4
    ((float4*)g_X)[i] = tf4(((const float4*)x)[i]);
}
__global__ __launch_bounds__(256) void round_w_kernel(
    const float* __restrict__ Wq, const float* __restrict__ Wk,
    const float* __restrict__ Wv, const float* __restrict__ Wo)
{
    int i = blockIdx.x * 256 + threadIdx.x;     // 262,144 float4 per tensor
    int z = blockIdx.y;
    const float* src = (z==0)?Wq:(z==1)?Wk:(z==2)?Wv:Wo;
    float* dst       = (z==0)?g_WrQ:(z==1)?g_WrK:(z==2)?g_WrV:g_WrO;
    ((float4*)dst)[i] = tf4(((const float4*)src)[i]);
}

// ---------------------------------------------------------------------------
// GEMM smem geometry (R5-proven): A [128][36] ldsm, B [32][136] scalar LDS.
// ---------------------------------------------------------------------------
#define GEMM_SMEM ((2*(128*36) + 2*(32*136)) * 4)   // 71680 B

// softmax scale folded into Q: 1/sqrt(64) * log2(e)
#define QSCL (0.125f * 1.4426950408889634f)

// ---------------------------------------------------------------------------
// Kernel 1: QKV projection. grid (32, 8, 3), 128x128 tiles.
// Q written pre-scaled by QSCL; V written TRANSPOSED [b][h][e][s].
// ---------------------------------------------------------------------------
__global__ __launch_bounds__(256) void qkv_kernel(
    const float* __restrict__ bq, const float* __restrict__ bk, const float* __restrict__ bv)
{
    extern __shared__ float sm[];
    float* Abuf[2] = { sm,        sm + 4608 };
    float* Bbuf[2] = { sm + 9216, sm + 9216 + 4352 };

    const int tid  = threadIdx.x;
    const int warp = tid >> 5, lane = tid & 31;
    const int g = lane >> 2, tg = lane & 3;
    const int wm = warp >> 1, wn = warp & 1;
    const int row0 = blockIdx.x * 128;
    const int col0 = blockIdx.y * 128;
    const int z = blockIdx.z;

    const float* W    = (z==0)?g_WrQ:(z==1)?g_WrK:g_WrV;
    const float* bias = (z==0)?bq:(z==1)?bk:bv;

    const int rA  = tid >> 3;            // 0..31 (+32u)
    const int kqA = (tid & 7) * 4;
    const int kB  = warp;                // +8u k rows
    const int cB  = lane * 4;
    const int ccg = col0 + cB;
    const int bh  = ccg >> 6, be = ccg & 63;
    const int a_r = ((lane >> 3) & 1) * 8 + (lane & 7);
    const int a_k = ((lane >> 4) & 1) * 4;

    float acc[2][8][4];
    #pragma unroll
    for (int i = 0; i < 2; i++)
        #pragma unroll
        for (int j = 0; j < 8; j++)
            #pragma unroll
            for (int k = 0; k < 4; k++) acc[i][j][k] = 0.f;

    #pragma unroll
    for (int u = 0; u < 4; u++)
        cpa16(Abuf[0] + (rA + 32*u) * 36 + kqA,
              g_X + (size_t)(row0 + rA + 32*u) * DM + kqA);
    #pragma unroll
    for (int u = 0; u < 4; u++)
        cpa16(Bbuf[0] + (kB + 8*u) * 136 + cB,
              W + ((size_t)bh * DM + kB + 8*u) * DHD + be);
    CP_COMMIT();

    for (int s = 0; s < 32; s++) {
        CP_WAIT0();
        __syncthreads();
        if (s < 31) {
            const int k0 = (s + 1) * 32;
            float* An = Abuf[(s+1) & 1];
            float* Bn = Bbuf[(s+1) & 1];
            #pragma unroll
            for (int u = 0; u < 4; u++)
                cpa16(An + (rA + 32*u) * 36 + kqA,
                      g_X + (size_t)(row0 + rA + 32*u) * DM + k0 + kqA);
            #pragma unroll
            for (int u = 0; u < 4; u++)
                cpa16(Bn + (kB + 8*u) * 136 + cB,
                      W + ((size_t)bh * DM + k0 + kB + 8*u) * DHD + be);
            CP_COMMIT();
        }
        const float* Acur = Abuf[s & 1];
        const float* Bcur = Bbuf[s & 1];
        #pragma unroll
        for (int ks = 0; ks < 4; ks++) {
            unsigned x0,x1,x2,x3, y0,y1,y2,y3;
            ldsm4(x0,x1,x2,x3, Acur + (wm*32      + a_r) * 36 + ks*8 + a_k);
            ldsm4(y0,y1,y2,y3, Acur + (wm*32 + 16 + a_r) * 36 + ks*8 + a_k);
            #pragma unroll
            for (int nt = 0; nt < 8; nt++) {
                int c = wn * 64 + nt * 8 + g;
                unsigned b0 = fu(Bcur[(ks*8 + tg    ) * 136 + c]);
                unsigned b1 = fu(Bcur[(ks*8 + tg + 4) * 136 + c]);
                mma8(acc[0][nt], x0,x1,x2,x3, b0,b1);
                mma8(acc[1][nt], y0,y1,y2,y3, b0,b1);
            }
        }
    }

    // Epilogue. Q: *QSCL then round. K: round. V: round + transpose to [b][h][e][s].
    const float sc = (z == 0) ? QSCL : 1.0f;
    #pragma unroll
    for (int mt = 0; mt < 2; mt++) {
        int r = row0 + wm * 32 + mt * 16 + g;
        int b_ = r >> 11, sq = r & 2047;
        #pragma unroll
        for (int nt = 0; nt < 8; nt++) {
            int cg = col0 + wn * 64 + nt * 8 + tg * 2;
            int h = cg >> 6, e = cg & 63;
            float bv0 = bias[cg], bv1 = bias[cg + 1];
            float v0 = to_tf32((acc[mt][nt][0] + bv0) * sc);
            float v1 = to_tf32((acc[mt][nt][1] + bv1) * sc);
            float v2 = to_tf32((acc[mt][nt][2] + bv0) * sc);
            float v3 = to_tf32((acc[mt][nt][3] + bv1) * sc);
            if (z == 2) {
                size_t base = ((size_t)(b_ * NH + h) * DHD + e) * SEQ;
                g_V[base + sq]           = v0;
                g_V[base + SEQ + sq]     = v1;
                g_V[base + sq + 8]       = v2;
                g_V[base + SEQ + sq + 8] = v3;
            } else {
                float* Out = z ? g_K : g_Q;
                size_t base = ((size_t)(b_ * NH + h) * SEQ + sq) * DHD + e;
                *(float2*)(Out + base)            = make_float2(v0, v1);
                *(float2*)(Out + base + 8 * DHD)  = make_float2(v2, v3);
            }
        }
    }
}

// ---------------------------------------------------------------------------
// Kernel 2: causal flash attention, 256 threads, 128-row q-tiles.
// K smem [s][e] ldsm; V smem [e][s] ldsm; P through smem (ldsm A-frags).
// Q pre-scaled by QSCL (scores already in base-2 domain).
// ---------------------------------------------------------------------------
#define KS_STRIDE 68
#define VT_STRIDE 132
#define PS_STRIDE 132
#define ATTN_SMEM ((128*KS_STRIDE + 64*VT_STRIDE + 128*PS_STRIDE) * 4)  // 136192 B

__global__ __launch_bounds__(256, 1) void attn_kernel()
{
    extern __shared__ float sma[];
    float* Ks  = sma;
    float* VTs = Ks + 128 * KS_STRIDE;
    float* Ps  = VTs + 64 * VT_STRIDE;

    const int tid  = threadIdx.x;
    const int warp = tid >> 5, lane = tid & 31;
    const int g = lane >> 2, tg = lane & 3;
    const int a_r = ((lane >> 3) & 1) * 8 + (lane & 7);
    const int a_k = ((lane >> 4) & 1) * 4;
    const int k_c = ((lane >> 4) & 1) * 8 + (lane & 7);
    const int k_k = ((lane >> 3) & 1) * 4;

    const int idx = blockIdx.x;
    const int qt  = 15 - (idx >> 5);        // heaviest q-tiles first
    const int bh  = idx & 31;

    const float* Qp = g_Q + (size_t)bh * SEQ * DHD;
    const float* Kp = g_K + (size_t)bh * SEQ * DHD;
    const float* Vp = g_V + (size_t)bh * SEQ * DHD;   // [e][s]

    const int qrow = qt * 128 + warp * 16 + g;
    const int prow = warp * 16 + g;

    // Q fragments (pre-rounded, pre-scaled in gmem)
    unsigned qa[8][4];
    #pragma unroll
    for (int ks = 0; ks < 8; ks++) {
        qa[ks][0] = fu(Qp[(size_t)(qrow    ) * DHD + ks * 8 + tg    ]);
        qa[ks][1] = fu(Qp[(size_t)(qrow + 8) * DHD + ks * 8 + tg    ]);
        qa[ks][2] = fu(Qp[(size_t)(qrow    ) * DHD + ks * 8 + tg + 4]);
        qa[ks][3] = fu(Qp[(size_t)(qrow + 8) * DHD + ks * 8 + tg + 4]);
    }

    float m0 = -1e30f, m1 = -1e30f, l0 = 0.f, l1 = 0.f;
    float o[8][4];
    #pragma unroll
    for (int nt = 0; nt < 8; nt++)
        #pragma unroll
        for (int cc = 0; cc < 4; cc++) o[nt][cc] = 0.f;

    // prologue: stage K(0) [s][e], V(0) transposed [e][s]
    {
        const float4* K4 = (const float4*)Kp;
        #pragma unroll
        for (int u = 0; u < 8; u++) {
            int i = tid + u * 256;
            int r = i >> 4, q = i & 15;
            cpa16(&Ks[r * KS_STRIDE + q * 4], K4 + i);
        }
        CP_COMMIT();
        #pragma unroll
        for (int u = 0; u < 8; u++) {
            int i = tid + u * 256;              // 2048 float4: 64 e-rows x 32 s-f4
            int rv = i >> 5, qv = i & 31;
            cpa16(&VTs[rv * VT_STRIDE + qv * 4], Vp + (size_t)rv * SEQ + qv * 4);
        }
        CP_COMMIT();
    }

    for (int j = 0; j <= qt; j++) {
        CP_WAIT1();                       // K(j) landed
        __syncthreads();

        // S = Q K^T  (scores pre-scaled via Q)
        float sacc[16][4];
        #pragma unroll
        for (int nt = 0; nt < 16; nt++)
            #pragma unroll
            for (int cc = 0; cc < 4; cc++) sacc[nt][cc] = 0.f;

        #pragma unroll
        for (int ntp = 0; ntp < 8; ntp++) {
            #pragma unroll
            for (int ks = 0; ks < 8; ks++) {
                unsigned b0,b1,b2,b3;
                ldsm4(b0,b1,b2,b3, Ks + (ntp*16 + k_c) * KS_STRIDE + ks*8 + k_k);
                mma8(sacc[2*ntp    ], qa[ks][0],qa[ks][1],qa[ks][2],qa[ks][3], b0,b1);
                mma8(sacc[2*ntp + 1], qa[ks][0],qa[ks][1],qa[ks][2],qa[ks][3], b2,b3);
            }
        }
        __syncthreads();                  // all warps done reading Ks
        if (j < qt) {                     // prefetch K(j+1)
            const float4* K4 = (const float4*)(Kp + (size_t)(j+1) * 128 * DHD);
            #pragma unroll
            for (int u = 0; u < 8; u++) {
                int i = tid + u * 256;
                int r = i >> 4, q = i & 15;
                cpa16(&Ks[r * KS_STRIDE + q * 4], K4 + i);
            }
            CP_COMMIT();
        }

        // causal mask (diagonal tile only)
        if (j == qt) {
            #pragma unroll
            for (int nt = 0; nt < 16; nt++) {
                int kc = j * 128 + nt * 8 + tg * 2;
                if (kc     > qrow    ) sacc[nt][0] = -1e30f;
                if (kc + 1 > qrow    ) sacc[nt][1] = -1e30f;
                if (kc     > qrow + 8) sacc[nt][2] = -1e30f;
                if (kc + 1 > qrow + 8) sacc[nt][3] = -1e30f;
            }
        }

        // row max (quad butterfly)
        float rm0 = -1e30f, rm1 = -1e30f;
        #pragma unroll
        for (int nt = 0; nt < 16; nt++) {
            rm0 = fmaxf(rm0, fmaxf(sacc[nt][0], sacc[nt][1]));
            rm1 = fmaxf(rm1, fmaxf(sacc[nt][2], sacc[nt][3]));
        }
        rm0 = fmaxf(rm0, __shfl_xor_sync(0xffffffffu, rm0, 1));
        rm0 = fmaxf(rm0, __shfl_xor_sync(0xffffffffu, rm0, 2));
        rm1 = fmaxf(rm1, __shfl_xor_sync(0xffffffffu, rm1, 1));
        rm1 = fmaxf(rm1, __shfl_xor_sync(0xffffffffu, rm1, 2));

        float mn0 = fmaxf(m0, rm0), mn1 = fmaxf(m1, rm1);
        float al0 = fast_ex2(m0 - mn0), al1 = fast_ex2(m1 - mn1);
        l0 *= al0; l1 *= al1;
        #pragma unroll
        for (int nt = 0; nt < 8; nt++) {
            o[nt][0] *= al0; o[nt][1] *= al0;
            o[nt][2] *= al1; o[nt][3] *= al1;
        }

        // P = exp2(s - m), tf32 to smem, accumulate row sums
        float rs0 = 0.f, rs1 = 0.f;
        #pragma unroll
        for (int nt = 0; nt < 16; nt++) {
            float p0 = fast_ex2(sacc[nt][0] - mn0);
            float p1 = fast_ex2(sacc[nt][1] - mn0);
            float p2 = fast_ex2(sacc[nt][2] - mn1);
            float p3 = fast_ex2(sacc[nt][3] - mn1);
            rs0 += p0 + p1; rs1 += p2 + p3;
            *(float2*)&Ps[(prow    ) * PS_STRIDE + nt * 8 + tg * 2] =
                make_float2(to_tf32(p0), to_tf32(p1));
            *(float2*)&Ps[(prow + 8) * PS_STRIDE + nt * 8 + tg * 2] =
                make_float2(to_tf32(p2), to_tf32(p3));
        }
        rs0 += __shfl_xor_sync(0xffffffffu, rs0, 1);
        rs0 += __shfl_xor_sync(0xffffffffu, rs0, 2);
        rs1 += __shfl_xor_sync(0xffffffffu, rs1, 1);
        rs1 += __shfl_xor_sync(0xffffffffu, rs1, 2);
        l0 += rs0; l1 += rs1;
        m0 = mn0;  m1 = mn1;

        __syncwarp();                     // Ps writes visible to own warp's ldsm

        // preload P A-frags (reuses dead sacc registers)
        unsigned pf[16][4];
        #pragma unroll
        for (int ks = 0; ks < 16; ks++)
            ldsm4(pf[ks][0], pf[ks][1], pf[ks][2], pf[ks][3],
                  Ps + (warp*16 + a_r) * PS_STRIDE + ks*8 + a_k);

        // wait for V(j), then barrier for visibility
        if (j < qt) { CP_WAIT1(); } else { CP_WAIT0(); }
        __syncthreads();

        // O += P V : both operands via ldsm (V from [e][s] tile)
        #pragma unroll
        for (int ntp = 0; ntp < 4; ntp++) {
            #pragma unroll
            for (int ks = 0; ks < 16; ks++) {
                unsigned b0,b1,b2,b3;
                ldsm4(b0,b1,b2,b3, VTs + (ntp*16 + k_c) * VT_STRIDE + ks*8 + k_k);
                mma8(o[2*ntp    ], pf[ks][0],pf[ks][1],pf[ks][2],pf[ks][3], b0,b1);
                mma8(o[2*ntp + 1], pf[ks][0],pf[ks][1],pf[ks][2],pf[ks][3], b2,b3);
            }
        }
        __syncthreads();                  // all warps done reading VTs
        if (j < qt) {                     // prefetch V(j+1) [e][s]
            #pragma unroll
            for (int u = 0; u < 8; u++) {
                int i = tid + u * 256;
                int rv = i >> 5, qv = i & 31;
                cpa16(&VTs[rv * VT_STRIDE + qv * 4],
                      Vp + (size_t)rv * SEQ + (j+1) * 128 + qv * 4);
            }
            CP_COMMIT();
        }
    }

    // normalize + round + write Z in [b][s][h*64+e] layout
    float inv0 = 1.f / l0, inv1 = 1.f / l1;
    const int b_ = bh >> 4, h = bh & 15;
    size_t base = ((size_t)b_ * SEQ + qrow) * DM + h * DHD;
    #pragma unroll
    for (int nt = 0; nt < 8; nt++) {
        int e = nt * 8 + tg * 2;
        *(float2*)(g_Z + base + e) =
            make_float2(to_tf32(o[nt][0] * inv0), to_tf32(o[nt][1] * inv0));
        *(float2*)(g_Z + base + (size_t)8 * DM + e) =
            make_float2(to_tf32(o[nt][2] * inv1), to_tf32(o[nt][3] * inv1));
    }
}

// ---------------------------------------------------------------------------
// Kernel 3: output projection (same structure as qkv).
// ---------------------------------------------------------------------------
__global__ __launch_bounds__(256) void oproj_kernel(
    const float* __restrict__ bo, float* __restrict__ out)
{
    extern __shared__ float sm[];
    float* Abuf[2] = { sm,        sm + 4608 };
    float* Bbuf[2] = { sm + 9216, sm + 9216 + 4352 };

    const int tid  = threadIdx.x;
    const int warp = tid >> 5, lane = tid & 31;
    const int g = lane >> 2, tg = lane & 3;
    const int wm = warp >> 1, wn = warp & 1;
    const int row0 = blockIdx.x * 128;
    const int col0 = blockIdx.y * 128;

    const int rA  = tid >> 3;
    const int kqA = (tid & 7) * 4;
    const int kB  = warp;
    const int cB  = lane * 4;
    const int a_r = ((lane >> 3) & 1) * 8 + (lane & 7);
    const int a_k = ((lane >> 4) & 1) * 4;

    float acc[2][8][4];
    #pragma unroll
    for (int i = 0; i < 2; i++)
        #pragma unroll
        for (int j = 0; j < 8; j++)
            #pragma unroll
            for (int k = 0; k < 4; k++) acc[i][j][k] = 0.f;

    #pragma unroll
    for (int u = 0; u < 4; u++)
        cpa16(Abuf[0] + (rA + 32*u) * 36 + kqA,
              g_Z + (size_t)(row0 + rA + 32*u) * DM + kqA);
    #pragma unroll
    for (int u = 0; u < 4; u++)
        cpa16(Bbuf[0] + (kB + 8*u) * 136 + cB,
              g_WrO + (size_t)(kB + 8*u) * DM + col0 + cB);
    CP_COMMIT();

    for (int s = 0; s < 32; s++) {
        CP_WAIT0();
        __syncthreads();
        if (s < 31) {
            const int k0 = (s + 1) * 32;
            float* An = Abuf[(s+1) & 1];
            float* Bn = Bbuf[(s+1) & 1];
            #pragma unroll
            for (int u = 0; u < 4; u++)
                cpa16(An + (rA + 32*u) * 36 + kqA,
                      g_Z + (size_t)(row0 + rA + 32*u) * DM + k0 + kqA);
            #pragma unroll
            for (int u = 0; u < 4; u++)
                cpa16(Bn + (kB + 8*u) * 136 + cB,
                      g_WrO + (size_t)(k0 + kB + 8*u) * DM + col0 + cB);
            CP_COMMIT();
        }
        const float* Acur = Abuf[s & 1];
        const float* Bcur = Bbuf[s & 1];
        #pragma unroll
        for (int ks = 0; ks < 4; ks++) {
            unsigned x0,x1,x2,x3, y0,y1,y2,y3;
            ldsm4(x0,x1,x2,x3, Acur + (wm*32      + a_r) * 36 + ks*8 + a_k);
            ldsm4(y0,y1,y2,y3, Acur + (wm*32 + 16 + a_r) * 36 + ks*8 + a_k);
            #pragma unroll
            for (int nt = 0; nt < 8; nt++) {
                int c = wn * 64 + nt * 8 + g;
                unsigned b0 = fu(Bcur[(ks*8 + tg    ) * 136 + c]);
                unsigned b1 = fu(Bcur[(ks*8 + tg + 4) * 136 + c]);
                mma8(acc[0][nt], x0,x1,x2,x3, b0,b1);
                mma8(acc[1][nt], y0,y1,y2,y3, b0,b1);
            }
        }
    }

    #pragma unroll
    for (int mt = 0; mt < 2; mt++) {
        int r = row0 + wm * 32 + mt * 16 + g;
        #pragma unroll
        for (int nt = 0; nt < 8; nt++) {
            int cg = col0 + wn * 64 + nt * 8 + tg * 2;
            float bv0 = bo[cg], bv1 = bo[cg + 1];
            *(float2*)(out + (size_t)(r    ) * DM + cg) =
                make_float2(acc[mt][nt][0] + bv0, acc[mt][nt][1] + bv1);
            *(float2*)(out + (size_t)(r + 8) * DM + cg) =
                make_float2(acc[mt][nt][2] + bv0, acc[mt][nt][3] + bv1);
        }
    }
}

// ---------------------------------------------------------------------------
extern "C" void kernel_launch(void* const* d_in, const int* in_sizes, int n_in,
                              void* d_out, int out_size)
{
    (void)in_sizes; (void)n_in; (void)out_size;
    const float* x  = (const float*)d_in[0];
    const float* Wq = (const float*)d_in[1];
    const float* Wk = (const float*)d_in[2];
    const float* Wv = (const float*)d_in[3];
    const float* Wo = (const float*)d_in[4];
    const float* bq = (const float*)d_in[5];
    const float* bk = (const float*)d_in[6];
    const float* bv = (const float*)d_in[7];
    const float* bo = (const float*)d_in[8];
    float* out = (float*)d_out;

    static bool attr_done = false;
    if (!attr_done) {
        cudaFuncSetAttribute(qkv_kernel,
            cudaFuncAttributeMaxDynamicSharedMemorySize, GEMM_SMEM);
        cudaFuncSetAttribute(attn_kernel,
            cudaFuncAttributeMaxDynamicSharedMemorySize, ATTN_SMEM);
        cudaFuncSetAttribute(oproj_kernel,
            cudaFuncAttributeMaxDynamicSharedMemorySize, GEMM_SMEM);
        attr_done = true;
    }

    round_x_kernel<<<4096, 256>>>(x);
    dim3 grw(1024, 4);
    round_w_kernel<<<grw, 256>>>(Wq, Wk, Wv, Wo);

    dim3 g1(32, 8, 3);
    qkv_kernel<<<g1, 256, GEMM_SMEM>>>(bq, bk, bv);

    attn_kernel<<<512, 256, ATTN_SMEM>>>();

    dim3 g3(32, 8);
    oproj_kernel<<<g3, 256, GEMM_SMEM>>>(bo, out);
}